// round 4
// baseline (speedup 1.0000x reference)
#include <cuda_runtime.h>

// VectorQuantization: N=32768 rows of D=64 vs K=1024 codes.
// out = [quantized (N*D) | indices as float (N) | commitment_loss (1)]
//
// R4: GEMM-style register tiling. Thread tile = 8 rows x 8 codes, row-pairs
// packed in f32x2 accumulators. x transposed in smem, w pre-duplicated (w,w)
// in smem. 16 code-splits, shfl.bfly merge across code groups.
// Rounding invariants (xnorm/wnorm sequential-in-d; dist = (xn+wn)-(2*dot))
// identical to R1-R3 which passed at rel_err 1.2e-7.

#define NROWS 32768
#define D     64
#define K     1024
#define CB    64                    // codes per block (split width)
#define RB    128                   // rows per block
#define SPL   (K / CB)              // 16 splits
#define TPB   128                   // threads per block
#define NBLKM ((NROWS / RB) * SPL)  // 4096 main blocks
#define EPB   256
#define NEPI  (NROWS / EPB)         // 128 epilogue blocks
#define SMEM_X   (D * RB * 4)             // 32768: x_t[d][r] f32
#define SMEM_WD  (D * CB * 8)             // 32768: w_dup[d][c] f32x2
#define SMEM_ALL (SMEM_X + SMEM_WD + RB * 4 + CB * 4)  // 66304

__device__ float g_best[SPL * NROWS];
__device__ int   g_bidx[SPL * NROWS];
__device__ float g_partial[NEPI];

static __device__ __forceinline__ unsigned long long ffma2(unsigned long long a,
                                                           unsigned long long b,
                                                           unsigned long long c) {
    unsigned long long d;
    asm("fma.rn.f32x2 %0, %1, %2, %3;" : "=l"(d) : "l"(a), "l"(b), "l"(c));
    return d;
}
static __device__ __forceinline__ unsigned long long pack2(float lo, float hi) {
    unsigned long long r;
    asm("mov.b64 %0, {%1, %2};" : "=l"(r) : "f"(lo), "f"(hi));
    return r;
}
static __device__ __forceinline__ void unpack2(unsigned long long v, float& lo, float& hi) {
    asm("mov.b64 {%0, %1}, %2;" : "=f"(lo), "=f"(hi) : "l"(v));
}

// ---- Kernel A: 128-row x 64-code tile per block, argmin candidates --------
__global__ void __launch_bounds__(TPB) vq_main(const float* __restrict__ x,
                                               const float* __restrict__ w) {
    extern __shared__ char smem_raw[];
    float*              sx  = reinterpret_cast<float*>(smem_raw);               // [D][RB]
    unsigned long long* swd = reinterpret_cast<unsigned long long*>(smem_raw + SMEM_X); // [D][CB]
    float*              sxn = reinterpret_cast<float*>(smem_raw + SMEM_X + SMEM_WD);    // [RB]
    float*              swn = sxn + RB;                                                  // [CB]

    const int tid    = threadIdx.x;
    const int split  = blockIdx.x & (SPL - 1);
    const int rowblk = blockIdx.x >> 4;
    const int row0   = rowblk * RB;
    const int k0     = split * CB;

    // ---- stage x (one row per thread), xnorm sequential-in-d (as R1) ----
    {
        const float4* xr = reinterpret_cast<const float4*>(x + (size_t)(row0 + tid) * D);
        float s = 0.f;
#pragma unroll
        for (int i = 0; i < 16; i++) {
            float4 v = xr[i];
            s = __fadd_rn(s, __fmul_rn(v.x, v.x));
            s = __fadd_rn(s, __fmul_rn(v.y, v.y));
            s = __fadd_rn(s, __fmul_rn(v.z, v.z));
            s = __fadd_rn(s, __fmul_rn(v.w, v.w));
            sx[(4 * i + 0) * RB + tid] = v.x;
            sx[(4 * i + 1) * RB + tid] = v.y;
            sx[(4 * i + 2) * RB + tid] = v.z;
            sx[(4 * i + 3) * RB + tid] = v.w;
        }
        sxn[tid] = s;
    }
    // ---- stage w duplicated (one code per thread, tid<64), wnorm as R1 ----
    if (tid < CB) {
        const float4* wr = reinterpret_cast<const float4*>(w + (size_t)(k0 + tid) * D);
        float s = 0.f;
#pragma unroll
        for (int i = 0; i < 16; i++) {
            float4 v = wr[i];
            s = __fadd_rn(s, __fmul_rn(v.x, v.x));
            s = __fadd_rn(s, __fmul_rn(v.y, v.y));
            s = __fadd_rn(s, __fmul_rn(v.z, v.z));
            s = __fadd_rn(s, __fmul_rn(v.w, v.w));
            swd[(4 * i + 0) * CB + tid] = pack2(v.x, v.x);
            swd[(4 * i + 1) * CB + tid] = pack2(v.y, v.y);
            swd[(4 * i + 2) * CB + tid] = pack2(v.z, v.z);
            swd[(4 * i + 3) * CB + tid] = pack2(v.w, v.w);
        }
        swn[tid] = s;
    }
    __syncthreads();

    const int rg = tid >> 3;   // 0..15: row group (8 rows)
    const int cg = tid & 7;    // 0..7 : code group (8 codes); consecutive lanes

    unsigned long long acc[4][8];
#pragma unroll
    for (int rp = 0; rp < 4; rp++)
#pragma unroll
        for (int c = 0; c < 8; c++) acc[rp][c] = 0ull;

#pragma unroll 8
    for (int d = 0; d < D; d++) {
        const ulonglong2* xp = reinterpret_cast<const ulonglong2*>(sx + d * RB + rg * 8);
        ulonglong2 xa = xp[0], xb = xp[1];
        unsigned long long xrp[4] = {xa.x, xa.y, xb.x, xb.y};
        const ulonglong2* wp = reinterpret_cast<const ulonglong2*>(swd + d * CB + cg * 8);
        ulonglong2 w01 = wp[0], w23 = wp[1], w45 = wp[2], w67 = wp[3];
        unsigned long long wv[8] = {w01.x, w01.y, w23.x, w23.y,
                                    w45.x, w45.y, w67.x, w67.y};
#pragma unroll
        for (int c = 0; c < 8; c++)
#pragma unroll
            for (int rp = 0; rp < 4; rp++)
                acc[rp][c] = ffma2(xrp[rp], wv[c], acc[rp][c]);
    }

    // ---- tail: dists + per-thread argmin over 8 codes ----
    float xnr[8];
    {
        float4 t0 = *reinterpret_cast<const float4*>(sxn + rg * 8);
        float4 t1 = *reinterpret_cast<const float4*>(sxn + rg * 8 + 4);
        xnr[0] = t0.x; xnr[1] = t0.y; xnr[2] = t0.z; xnr[3] = t0.w;
        xnr[4] = t1.x; xnr[5] = t1.y; xnr[6] = t1.z; xnr[7] = t1.w;
    }
    float bb[8];
    int   bi[8];
#pragma unroll
    for (int j = 0; j < 8; j++) { bb[j] = 3.4e38f; bi[j] = k0; }

#pragma unroll
    for (int c = 0; c < 8; c++) {
        float wn = swn[cg * 8 + c];
        int cglob = k0 + cg * 8 + c;
#pragma unroll
        for (int rp = 0; rp < 4; rp++) {
            float d0, d1;
            unpack2(acc[rp][c], d0, d1);
            // Reference rounding: (||x||^2 + ||e||^2) - (2.0 * dot).
            float dist0 = __fsub_rn(__fadd_rn(xnr[2 * rp],     wn), __fmul_rn(2.0f, d0));
            float dist1 = __fsub_rn(__fadd_rn(xnr[2 * rp + 1], wn), __fmul_rn(2.0f, d1));
            if (dist0 < bb[2 * rp])     { bb[2 * rp]     = dist0; bi[2 * rp]     = cglob; }
            if (dist1 < bb[2 * rp + 1]) { bb[2 * rp + 1] = dist1; bi[2 * rp + 1] = cglob; }
        }
    }

    // ---- merge across the 8 code groups (consecutive lanes) via shfl ----
#pragma unroll
    for (int off = 1; off < 8; off <<= 1) {
#pragma unroll
        for (int j = 0; j < 8; j++) {
            float ob = __shfl_xor_sync(0xffffffffu, bb[j], off);
            int   oi = __shfl_xor_sync(0xffffffffu, bi[j], off);
            // lowest code index wins ties
            if (ob < bb[j] || (ob == bb[j] && oi < bi[j])) { bb[j] = ob; bi[j] = oi; }
        }
    }
    if (cg == 0) {
#pragma unroll
        for (int j = 0; j < 8; j++) {
            g_best[split * NROWS + row0 + rg * 8 + j] = bb[j];
            g_bidx[split * NROWS + row0 + rg * 8 + j] = bi[j];
        }
    }
}

// ---- Kernel B: reduce splits, gather, STE output, loss partials ------------
__global__ void __launch_bounds__(EPB) vq_epi(const float* __restrict__ x,
                                              const float* __restrict__ w,
                                              float* __restrict__ out_q,
                                              float* __restrict__ out_idx,
                                              int has_idx) {
    __shared__ float s_red[EPB];
    const int tid = threadIdx.x;
    const int row = blockIdx.x * EPB + tid;

    float best = g_best[row];
    int bidx = g_bidx[row];
#pragma unroll
    for (int s = 1; s < SPL; s++) {
        float b = g_best[s * NROWS + row];
        int   i = g_bidx[s * NROWS + row];
        if (b < best) { best = b; bidx = i; }  // strict <: earlier split wins ties
    }

    const float4* wb   = reinterpret_cast<const float4*>(w + (size_t)bidx * D);
    const float4* xrow = reinterpret_cast<const float4*>(x + (size_t)row * D);
    float4* oq = reinterpret_cast<float4*>(out_q + (size_t)row * D);
    float lsum = 0.f;
#pragma unroll
    for (int i = 0; i < 16; i++) {
        float4 wv = wb[i];
        float4 xv = xrow[i];
        float4 dv, ov;
        dv.x = __fsub_rn(wv.x, xv.x);
        dv.y = __fsub_rn(wv.y, xv.y);
        dv.z = __fsub_rn(wv.z, xv.z);
        dv.w = __fsub_rn(wv.w, xv.w);
        ov.x = __fadd_rn(xv.x, dv.x);   // inputs + (quantized - inputs)
        ov.y = __fadd_rn(xv.y, dv.y);
        ov.z = __fadd_rn(xv.z, dv.z);
        ov.w = __fadd_rn(xv.w, dv.w);
        lsum += dv.x * dv.x + dv.y * dv.y + dv.z * dv.z + dv.w * dv.w;
        oq[i] = ov;
    }
    if (has_idx) out_idx[row] = (float)bidx;

    s_red[tid] = lsum;
    __syncthreads();
#pragma unroll
    for (int s = EPB / 2; s > 0; s >>= 1) {
        if (tid < s) s_red[tid] = __fadd_rn(s_red[tid], s_red[tid + s]);
        __syncthreads();
    }
    if (tid == 0) g_partial[blockIdx.x] = s_red[0];
}

// ---- Kernel C: final deterministic reduction -> commitment loss ------------
__global__ void vq_final(float* __restrict__ out_loss) {
    __shared__ float s[64];
    int tid = threadIdx.x;  // 64 threads
    s[tid] = __fadd_rn(g_partial[tid], g_partial[tid + 64]);
    __syncthreads();
    for (int st = 32; st > 0; st >>= 1) {
        if (tid < st) s[tid] = __fadd_rn(s[tid], s[tid + st]);
        __syncthreads();
    }
    if (tid == 0) {
        float mean = s[0] / 2097152.0f;  // exact: power-of-two divisor
        *out_loss = 0.25f * (mean + mean);
    }
}

extern "C" void kernel_launch(void* const* d_in, const int* in_sizes, int n_in,
                              void* d_out, int out_size) {
    const float* x;
    const float* w;
    if (n_in >= 2 && in_sizes[0] == K * D && in_sizes[1] != K * D) {
        w = (const float*)d_in[0];
        x = (const float*)d_in[1];
    } else {
        x = (const float*)d_in[0];
        w = (const float*)d_in[1];
    }

    float* out = (float*)d_out;
    const long ND = (long)NROWS * D;
    if (out_size < ND) return;

    int has_idx  = out_size >= ND + NROWS;
    int has_loss = out_size >= ND + NROWS + 1;

    cudaFuncSetAttribute(vq_main, cudaFuncAttributeMaxDynamicSharedMemorySize, SMEM_ALL);
    vq_main<<<NBLKM, TPB, SMEM_ALL>>>(x, w);
    vq_epi<<<NEPI, EPB>>>(x, w, out, out + ND, has_idx);
    if (has_loss) vq_final<<<1, 64>>>(out + ND + NROWS);
}

// round 6
// speedup vs baseline: 2.1539x; 2.1539x over previous
#include <cuda_runtime.h>

// VectorQuantization: N=32768 rows of D=64 vs K=1024 codes.
// out = [quantized (N*D) | indices as float (N) | commitment_loss (1)]
//
// R6: d-pair f32x2 packing; warp owns 16 rows x ALL 64 tile codes (fixes the
// R5 cross-warp row race). Thread tile 4 rows x 8 codes. All LDS 1-wavefront.
// Rounding invariants identical to R1-R4 (passed at rel_err 1.2e-7).

#define NROWS 32768
#define D     64
#define RB    64                    // rows per block
#define CBT   64                    // codes per tile
#define SPL   4                     // K splits
#define KTOT  1024
#define KPB   (KTOT / SPL)          // 256 codes per block
#define TILES (KPB / CBT)           // 4
#define TPB   128
#define NBLKM ((NROWS / RB) * SPL)  // 2048
#define EPB   256
#define NEPI  (NROWS / EPB)         // 128

__device__ float g_best[SPL * NROWS];
__device__ int   g_bidx[SPL * NROWS];
__device__ float g_partial[NEPI];

static __device__ __forceinline__ unsigned long long ffma2(unsigned long long a,
                                                           unsigned long long b,
                                                           unsigned long long c) {
    unsigned long long d;
    asm("fma.rn.f32x2 %0, %1, %2, %3;" : "=l"(d) : "l"(a), "l"(b), "l"(c));
    return d;
}
static __device__ __forceinline__ unsigned long long pack2(float lo, float hi) {
    unsigned long long r;
    asm("mov.b64 %0, {%1, %2};" : "=l"(r) : "f"(lo), "f"(hi));
    return r;
}
static __device__ __forceinline__ void unpack2(unsigned long long v, float& lo, float& hi) {
    asm("mov.b64 {%0, %1}, %2;" : "=f"(lo), "=f"(hi) : "l"(v));
}

// ---- Kernel A: 64-row x 256-code block, argmin candidates ------------------
__global__ void __launch_bounds__(TPB) vq_main(const float* __restrict__ x,
                                               const float* __restrict__ w) {
    // [dp][row] and [dp][code], f32x2 elements (d-pairs)
    __shared__ __align__(16) unsigned long long sx[32 * RB];    // 16 KB
    __shared__ __align__(16) unsigned long long swd[32 * CBT];  // 16 KB
    __shared__ float sxn[RB];
    __shared__ float swn[CBT];

    const int tid   = threadIdx.x;
    const int lane  = tid & 31;
    const int warp  = tid >> 5;          // 0..3: owns rows warp*16 .. +15
    const int split = blockIdx.x & (SPL - 1);
    const int row0  = (blockIdx.x >> 2) * RB;
    const int k0    = split * KPB;

    // ---- stage x (one row per thread, tid<64); xnorm sequential (as R1) ----
    if (tid < RB) {
        const float4* xr = reinterpret_cast<const float4*>(x + (size_t)(row0 + tid) * D);
        float s = 0.f;
#pragma unroll
        for (int i = 0; i < 16; i++) {
            float4 v = xr[i];
            s = __fadd_rn(s, __fmul_rn(v.x, v.x));
            s = __fadd_rn(s, __fmul_rn(v.y, v.y));
            s = __fadd_rn(s, __fmul_rn(v.z, v.z));
            s = __fadd_rn(s, __fmul_rn(v.w, v.w));
            sx[(2 * i) * RB + tid]     = pack2(v.x, v.y);
            sx[(2 * i + 1) * RB + tid] = pack2(v.z, v.w);
        }
        sxn[tid] = s;
    }
    __syncthreads();

    const int rg = lane >> 3;   // 0..3: row pair-group within warp
    const int cg = lane & 7;    // 0..7: code pair-group

    // thread rows (local): warp*16 + {2rg, 2rg+1, 8+2rg, 9+2rg}
    const int rl0 = warp * 16 + 2 * rg;
    const int rl2 = rl0 + 8;
    const float xnr[4] = {sxn[rl0], sxn[rl0 + 1], sxn[rl2], sxn[rl2 + 1]};

    float bb[4];
    int   bi[4];
#pragma unroll
    for (int r = 0; r < 4; r++) { bb[r] = 3.4e38f; bi[r] = k0; }

    const ulonglong2* sxu = reinterpret_cast<const ulonglong2*>(sx);
    const ulonglong2* swu = reinterpret_cast<const ulonglong2*>(swd);

    for (int tile = 0; tile < TILES; tile++) {
        const int kt = k0 + tile * CBT;
        __syncthreads();  // previous tile fully consumed
        if (tid < CBT) {
            const float4* wrp = reinterpret_cast<const float4*>(w + (size_t)(kt + tid) * D);
            float s = 0.f;
#pragma unroll
            for (int i = 0; i < 16; i++) {
                float4 v = wrp[i];
                s = __fadd_rn(s, __fmul_rn(v.x, v.x));
                s = __fadd_rn(s, __fmul_rn(v.y, v.y));
                s = __fadd_rn(s, __fmul_rn(v.z, v.z));
                s = __fadd_rn(s, __fmul_rn(v.w, v.w));
                swd[(2 * i) * CBT + tid]     = pack2(v.x, v.y);
                swd[(2 * i + 1) * CBT + tid] = pack2(v.z, v.w);
            }
            swn[tid] = s;
        }
        __syncthreads();

        unsigned long long acc[4][8];
#pragma unroll
        for (int r = 0; r < 4; r++)
#pragma unroll
            for (int c = 0; c < 8; c++) acc[r][c] = 0ull;

#pragma unroll 8
        for (int dp = 0; dp < 32; dp++) {
            // x: two LDS.128; 4 distinct addrs (rg) x 16B, 64B span each
            ulonglong2 xa = sxu[dp * 32 + warp * 8 + rg];       // rows 2rg, 2rg+1
            ulonglong2 xb = sxu[dp * 32 + warp * 8 + rg + 4];   // rows 8+2rg, 9+2rg
            unsigned long long xv[4] = {xa.x, xa.y, xb.x, xb.y};
            // w: four LDS.128; 8 distinct addrs (cg) x 16B, 128B span each
            ulonglong2 w0 = swu[dp * 32 + cg];                  // codes 2cg, 2cg+1
            ulonglong2 w1 = swu[dp * 32 + cg + 8];              // +16
            ulonglong2 w2 = swu[dp * 32 + cg + 16];             // +32
            ulonglong2 w3 = swu[dp * 32 + cg + 24];             // +48
            unsigned long long wv[8] = {w0.x, w0.y, w1.x, w1.y,
                                        w2.x, w2.y, w3.x, w3.y};
#pragma unroll
            for (int c = 0; c < 8; c++)
#pragma unroll
                for (int r = 0; r < 4; r++)
                    acc[r][c] = ffma2(xv[r], wv[c], acc[r][c]);
        }

        // tail: dists + per-thread argmin (cl ascending in c)
#pragma unroll
        for (int c = 0; c < 8; c++) {
            const int cl = 16 * (c >> 1) + 2 * cg + (c & 1);
            const float wn = swn[cl];
            const int cglob = kt + cl;
#pragma unroll
            for (int r = 0; r < 4; r++) {
                float lo, hi;
                unpack2(acc[r][c], lo, hi);
                float dot = __fadd_rn(lo, hi);
                // Reference rounding: (||x||^2 + ||e||^2) - (2.0 * dot).
                float dist = __fsub_rn(__fadd_rn(xnr[r], wn), __fmul_rn(2.0f, dot));
                if (dist < bb[r]) { bb[r] = dist; bi[r] = cglob; }
            }
        }
    }

    // merge across the 8 cg lanes (lexicographic: lowest index wins ties)
#pragma unroll
    for (int off = 1; off < 8; off <<= 1) {
#pragma unroll
        for (int r = 0; r < 4; r++) {
            float ob = __shfl_xor_sync(0xffffffffu, bb[r], off);
            int   oi = __shfl_xor_sync(0xffffffffu, bi[r], off);
            if (ob < bb[r] || (ob == bb[r] && oi < bi[r])) { bb[r] = ob; bi[r] = oi; }
        }
    }
    if (cg == 0) {
        const int rl[4] = {rl0, rl0 + 1, rl2, rl2 + 1};
#pragma unroll
        for (int r = 0; r < 4; r++) {
            g_best[split * NROWS + row0 + rl[r]] = bb[r];
            g_bidx[split * NROWS + row0 + rl[r]] = bi[r];
        }
    }
}

// ---- Kernel B: reduce splits, gather, STE output, loss partials ------------
__global__ void __launch_bounds__(EPB) vq_epi(const float* __restrict__ x,
                                              const float* __restrict__ w,
                                              float* __restrict__ out_q,
                                              float* __restrict__ out_idx,
                                              int has_idx) {
    __shared__ float s_red[EPB];
    const int tid = threadIdx.x;
    const int row = blockIdx.x * EPB + tid;

    float best = g_best[row];
    int bidx = g_bidx[row];
#pragma unroll
    for (int s = 1; s < SPL; s++) {
        float b = g_best[s * NROWS + row];
        int   i = g_bidx[s * NROWS + row];
        if (b < best) { best = b; bidx = i; }  // strict <: earlier split wins ties
    }

    const float4* wb   = reinterpret_cast<const float4*>(w + (size_t)bidx * D);
    const float4* xrow = reinterpret_cast<const float4*>(x + (size_t)row * D);
    float4* oq = reinterpret_cast<float4*>(out_q + (size_t)row * D);
    float lsum = 0.f;
#pragma unroll
    for (int i = 0; i < 16; i++) {
        float4 wv = wb[i];
        float4 xv = xrow[i];
        float4 dv, ov;
        dv.x = __fsub_rn(wv.x, xv.x);
        dv.y = __fsub_rn(wv.y, xv.y);
        dv.z = __fsub_rn(wv.z, xv.z);
        dv.w = __fsub_rn(wv.w, xv.w);
        ov.x = __fadd_rn(xv.x, dv.x);   // inputs + (quantized - inputs)
        ov.y = __fadd_rn(xv.y, dv.y);
        ov.z = __fadd_rn(xv.z, dv.z);
        ov.w = __fadd_rn(xv.w, dv.w);
        lsum += dv.x * dv.x + dv.y * dv.y + dv.z * dv.z + dv.w * dv.w;
        oq[i] = ov;
    }
    if (has_idx) out_idx[row] = (float)bidx;

    s_red[tid] = lsum;
    __syncthreads();
#pragma unroll
    for (int s = EPB / 2; s > 0; s >>= 1) {
        if (tid < s) s_red[tid] = __fadd_rn(s_red[tid], s_red[tid + s]);
        __syncthreads();
    }
    if (tid == 0) g_partial[blockIdx.x] = s_red[0];
}

// ---- Kernel C: final deterministic reduction -> commitment loss ------------
__global__ void vq_final(float* __restrict__ out_loss) {
    __shared__ float s[64];
    int tid = threadIdx.x;  // 64 threads
    s[tid] = __fadd_rn(g_partial[tid], g_partial[tid + 64]);
    __syncthreads();
    for (int st = 32; st > 0; st >>= 1) {
        if (tid < st) s[tid] = __fadd_rn(s[tid], s[tid + st]);
        __syncthreads();
    }
    if (tid == 0) {
        float mean = s[0] / 2097152.0f;  // exact: power-of-two divisor
        *out_loss = 0.25f * (mean + mean);
    }
}

extern "C" void kernel_launch(void* const* d_in, const int* in_sizes, int n_in,
                              void* d_out, int out_size) {
    const float* x;
    const float* w;
    if (n_in >= 2 && in_sizes[0] == KTOT * D && in_sizes[1] != KTOT * D) {
        w = (const float*)d_in[0];
        x = (const float*)d_in[1];
    } else {
        x = (const float*)d_in[0];
        w = (const float*)d_in[1];
    }

    float* out = (float*)d_out;
    const long ND = (long)NROWS * D;
    if (out_size < ND) return;

    int has_idx  = out_size >= ND + NROWS;
    int has_loss = out_size >= ND + NROWS + 1;

    vq_main<<<NBLKM, TPB>>>(x, w);
    vq_epi<<<NEPI, EPB>>>(x, w, out, out + ND, has_idx);
    if (has_loss) vq_final<<<1, 64>>>(out + ND + NROWS);
}

// round 7
// speedup vs baseline: 2.3914x; 1.1102x over previous
#include <cuda_runtime.h>

// VectorQuantization: N=32768 rows of D=64 vs K=1024 codes.
// out = [quantized (N*D) | indices as float (N) | commitment_loss (1)]
//
// R7: crossbar-cost-calibrated tiling. Thread tile 4 rows x 16 codes.
// x loads: full-spread LDS.128 (512B distinct, ~4.8cyc). w loads: broadcast
// LDS.128 (warp shares a 16-code chunk, ~2.5cyc). 29.6 crossbar cyc per
// 32 fma cyc per dp (vs 1.81 ratio in R6). Warps own disjoint code chunks,
// merged once via smem. Rounding invariants identical to passing rounds.

#define NROWS 32768
#define D     64
#define RB    128                   // rows per block
#define CBT   64                    // codes per tile
#define SPL   4                     // K splits
#define KTOT  1024
#define KPB   (KTOT / SPL)          // 256 codes per block
#define TILES (KPB / CBT)           // 4
#define TPB   128
#define NBLKM ((NROWS / RB) * SPL)  // 1024
#define EPB   256
#define NEPI  (NROWS / EPB)         // 128

#define SX_BYTES  (32 * RB * 8)     // 32768: x d-pairs [dp][row]
#define SWD_BYTES (32 * CBT * 8)    // 16384: w d-pairs [dp][code]
#define SXN_OFF   (SX_BYTES + SWD_BYTES)
#define SWN_OFF   (SXN_OFF + RB * 4)
#define SMEM_ALL  (SWN_OFF + CBT * 4)

__device__ float g_best[SPL * NROWS];
__device__ int   g_bidx[SPL * NROWS];
__device__ float g_partial[NEPI];

static __device__ __forceinline__ unsigned long long ffma2(unsigned long long a,
                                                           unsigned long long b,
                                                           unsigned long long c) {
    unsigned long long d;
    asm("fma.rn.f32x2 %0, %1, %2, %3;" : "=l"(d) : "l"(a), "l"(b), "l"(c));
    return d;
}
static __device__ __forceinline__ unsigned long long pack2(float lo, float hi) {
    unsigned long long r;
    asm("mov.b64 %0, {%1, %2};" : "=l"(r) : "f"(lo), "f"(hi));
    return r;
}
static __device__ __forceinline__ void unpack2(unsigned long long v, float& lo, float& hi) {
    asm("mov.b64 {%0, %1}, %2;" : "=f"(lo), "=f"(hi) : "l"(v));
}

// ---- Kernel A: 128-row x 256-code block ------------------------------------
__global__ void __launch_bounds__(TPB, 2) vq_main(const float* __restrict__ x,
                                                  const float* __restrict__ w) {
    extern __shared__ __align__(16) char smem_raw[];
    unsigned long long* sx  = reinterpret_cast<unsigned long long*>(smem_raw);             // [dp][row]
    unsigned long long* swd = reinterpret_cast<unsigned long long*>(smem_raw + SX_BYTES);  // [dp][code]
    float* sxn = reinterpret_cast<float*>(smem_raw + SXN_OFF);   // [RB]
    float* swn = reinterpret_cast<float*>(smem_raw + SWN_OFF);   // [CBT]
    // merge buffers overlay swd after the last tile (guarded by __syncthreads)
    float* m_b = reinterpret_cast<float*>(smem_raw + SX_BYTES);          // [4*RB]
    int*   m_i = reinterpret_cast<int*>(smem_raw + SX_BYTES + 4 * RB * 4); // [4*RB]

    const int tid   = threadIdx.x;
    const int lane  = tid & 31;
    const int warp  = tid >> 5;          // 0..3: code chunk warp*16 within tile
    const int split = blockIdx.x & (SPL - 1);
    const int row0  = (blockIdx.x >> 2) * RB;
    const int k0    = split * KPB;

    // ---- stage x (one row per thread); xnorm sequential-in-d (as R1) ----
    {
        const float4* xr = reinterpret_cast<const float4*>(x + (size_t)(row0 + tid) * D);
        float s = 0.f;
#pragma unroll
        for (int i = 0; i < 16; i++) {
            float4 v = xr[i];
            s = __fadd_rn(s, __fmul_rn(v.x, v.x));
            s = __fadd_rn(s, __fmul_rn(v.y, v.y));
            s = __fadd_rn(s, __fmul_rn(v.z, v.z));
            s = __fadd_rn(s, __fmul_rn(v.w, v.w));
            sx[(2 * i) * RB + tid]     = pack2(v.x, v.y);
            sx[(2 * i + 1) * RB + tid] = pack2(v.z, v.w);
        }
        sxn[tid] = s;
    }
    __syncthreads();

    // thread's 4 rows: 2*lane, 2*lane+1, 64+2*lane, 65+2*lane
    const int rlA = 2 * lane;
    const int rlB = 64 + 2 * lane;
    const float xnr[4] = {sxn[rlA], sxn[rlA + 1], sxn[rlB], sxn[rlB + 1]};

    float bb[4];
    int   bi[4];
#pragma unroll
    for (int r = 0; r < 4; r++) { bb[r] = 3.4e38f; bi[r] = k0; }

    const ulonglong2* sxu = reinterpret_cast<const ulonglong2*>(sx);
    const ulonglong2* swu = reinterpret_cast<const ulonglong2*>(swd);

    for (int tile = 0; tile < TILES; tile++) {
        const int kt = k0 + tile * CBT;
        __syncthreads();  // previous tile fully consumed
        if (tid < CBT) {
            const float4* wrp = reinterpret_cast<const float4*>(w + (size_t)(kt + tid) * D);
            float s = 0.f;
#pragma unroll
            for (int i = 0; i < 16; i++) {
                float4 v = wrp[i];
                s = __fadd_rn(s, __fmul_rn(v.x, v.x));
                s = __fadd_rn(s, __fmul_rn(v.y, v.y));
                s = __fadd_rn(s, __fmul_rn(v.z, v.z));
                s = __fadd_rn(s, __fmul_rn(v.w, v.w));
                swd[(2 * i) * CBT + tid]     = pack2(v.x, v.y);
                swd[(2 * i + 1) * CBT + tid] = pack2(v.z, v.w);
            }
            swn[tid] = s;
        }
        __syncthreads();

        unsigned long long acc[4][16];
#pragma unroll
        for (int r = 0; r < 4; r++)
#pragma unroll
            for (int c = 0; c < 16; c++) acc[r][c] = 0ull;

#pragma unroll 4
        for (int dp = 0; dp < 32; dp++) {
            // x: 2 full-spread LDS.128 (lane-contiguous 16B, 512B distinct)
            ulonglong2 xa = sxu[dp * 64 + lane];        // rows 2L, 2L+1
            ulonglong2 xb = sxu[dp * 64 + 32 + lane];   // rows 64+2L, 65+2L
            const unsigned long long xv[4] = {xa.x, xa.y, xb.x, xb.y};
            // w: 8 broadcast LDS.128 (all lanes same addr), 16 codes
#pragma unroll
            for (int j = 0; j < 8; j++) {
                ulonglong2 wp = swu[dp * 32 + warp * 8 + j];  // codes w*16+2j, +1
#pragma unroll
                for (int r = 0; r < 4; r++)
                    acc[r][2 * j]     = ffma2(xv[r], wp.x, acc[r][2 * j]);
#pragma unroll
                for (int r = 0; r < 4; r++)
                    acc[r][2 * j + 1] = ffma2(xv[r], wp.y, acc[r][2 * j + 1]);
            }
        }

        // tail: dists + per-thread argmin, codes ascending
#pragma unroll
        for (int c = 0; c < 16; c++) {
            const int cl = warp * 16 + c;
            const float wn = swn[cl];
            const int cglob = kt + cl;
#pragma unroll
            for (int r = 0; r < 4; r++) {
                float lo, hi;
                unpack2(acc[r][c], lo, hi);
                float dot = __fadd_rn(lo, hi);
                // Reference rounding: (||x||^2 + ||e||^2) - (2.0 * dot).
                float dist = __fsub_rn(__fadd_rn(xnr[r], wn), __fmul_rn(2.0f, dot));
                if (dist < bb[r]) { bb[r] = dist; bi[r] = cglob; }
            }
        }
    }

    // ---- cross-warp merge (warps own disjoint code chunks, same rows) ----
    __syncthreads();  // tails done; safe to overlay swd region
    m_b[warp * RB + rlA]     = bb[0];  m_i[warp * RB + rlA]     = bi[0];
    m_b[warp * RB + rlA + 1] = bb[1];  m_i[warp * RB + rlA + 1] = bi[1];
    m_b[warp * RB + rlB]     = bb[2];  m_i[warp * RB + rlB]     = bi[2];
    m_b[warp * RB + rlB + 1] = bb[3];  m_i[warp * RB + rlB + 1] = bi[3];
    __syncthreads();
    {
        float B = m_b[tid];
        int   I = m_i[tid];
#pragma unroll
        for (int ww = 1; ww < 4; ww++) {
            float b2 = m_b[ww * RB + tid];
            int   i2 = m_i[ww * RB + tid];
            if (b2 < B || (b2 == B && i2 < I)) { B = b2; I = i2; }  // lowest idx ties
        }
        g_best[split * NROWS + row0 + tid] = B;
        g_bidx[split * NROWS + row0 + tid] = I;
    }
}

// ---- Kernel B: reduce splits, gather, STE output, loss partials ------------
__global__ void __launch_bounds__(EPB) vq_epi(const float* __restrict__ x,
                                              const float* __restrict__ w,
                                              float* __restrict__ out_q,
                                              float* __restrict__ out_idx,
                                              int has_idx) {
    __shared__ float s_red[EPB];
    const int tid = threadIdx.x;
    const int row = blockIdx.x * EPB + tid;

    float best = g_best[row];
    int bidx = g_bidx[row];
#pragma unroll
    for (int s = 1; s < SPL; s++) {
        float b = g_best[s * NROWS + row];
        int   i = g_bidx[s * NROWS + row];
        if (b < best) { best = b; bidx = i; }  // strict <: earlier split wins ties
    }

    const float4* wb   = reinterpret_cast<const float4*>(w + (size_t)bidx * D);
    const float4* xrow = reinterpret_cast<const float4*>(x + (size_t)row * D);
    float4* oq = reinterpret_cast<float4*>(out_q + (size_t)row * D);
    float lsum = 0.f;
#pragma unroll
    for (int i = 0; i < 16; i++) {
        float4 wv = wb[i];
        float4 xv = xrow[i];
        float4 dv, ov;
        dv.x = __fsub_rn(wv.x, xv.x);
        dv.y = __fsub_rn(wv.y, xv.y);
        dv.z = __fsub_rn(wv.z, xv.z);
        dv.w = __fsub_rn(wv.w, xv.w);
        ov.x = __fadd_rn(xv.x, dv.x);   // inputs + (quantized - inputs)
        ov.y = __fadd_rn(xv.y, dv.y);
        ov.z = __fadd_rn(xv.z, dv.z);
        ov.w = __fadd_rn(xv.w, dv.w);
        lsum += dv.x * dv.x + dv.y * dv.y + dv.z * dv.z + dv.w * dv.w;
        oq[i] = ov;
    }
    if (has_idx) out_idx[row] = (float)bidx;

    s_red[tid] = lsum;
    __syncthreads();
#pragma unroll
    for (int s = EPB / 2; s > 0; s >>= 1) {
        if (tid < s) s_red[tid] = __fadd_rn(s_red[tid], s_red[tid + s]);
        __syncthreads();
    }
    if (tid == 0) g_partial[blockIdx.x] = s_red[0];
}

// ---- Kernel C: final deterministic reduction -> commitment loss ------------
__global__ void vq_final(float* __restrict__ out_loss) {
    __shared__ float s[64];
    int tid = threadIdx.x;  // 64 threads
    s[tid] = __fadd_rn(g_partial[tid], g_partial[tid + 64]);
    __syncthreads();
    for (int st = 32; st > 0; st >>= 1) {
        if (tid < st) s[tid] = __fadd_rn(s[tid], s[tid + st]);
        __syncthreads();
    }
    if (tid == 0) {
        float mean = s[0] / 2097152.0f;  // exact: power-of-two divisor
        *out_loss = 0.25f * (mean + mean);
    }
}

extern "C" void kernel_launch(void* const* d_in, const int* in_sizes, int n_in,
                              void* d_out, int out_size) {
    const float* x;
    const float* w;
    if (n_in >= 2 && in_sizes[0] == KTOT * D && in_sizes[1] != KTOT * D) {
        w = (const float*)d_in[0];
        x = (const float*)d_in[1];
    } else {
        x = (const float*)d_in[0];
        w = (const float*)d_in[1];
    }

    float* out = (float*)d_out;
    const long ND = (long)NROWS * D;
    if (out_size < ND) return;

    int has_idx  = out_size >= ND + NROWS;
    int has_loss = out_size >= ND + NROWS + 1;

    cudaFuncSetAttribute(vq_main, cudaFuncAttributeMaxDynamicSharedMemorySize, SMEM_ALL);
    vq_main<<<NBLKM, TPB, SMEM_ALL>>>(x, w);
    vq_epi<<<NEPI, EPB>>>(x, w, out, out + ND, has_idx);
    if (has_loss) vq_final<<<1, 64>>>(out + ND + NROWS);
}